// round 14
// baseline (speedup 1.0000x reference)
#include <cuda_runtime.h>
#include <cuda_fp16.h>
#include <cstdint>
#include <cstddef>
#include <type_traits>

// ============================================================================
// Quantized FFN via fp16-split warp-level mma.sync (HMMA) GEMMs.
//   GEMM1: h = q8(gelu_pwl(q8(x@w1+b1)))  -> h exact on q8 grid, stored fp16
//   GEMM2: out = q8(h@w2+b2)
// Split: hi=fp16(x), lo=fp16((x-hi)*2048).
// GEMM1 main: f32 chains of 16 k-steps flushed to per-thread SMEM masters.
// GEMM2 main: plain full-K f32 chain.
// Cross terms: f16-accumulator MMAs (x2048).
// R14: GEMM1 pipeline deepened to HALF-CHUNK (32-k) segments: 2 buffers x 2
// halves = 4 segments in flight, cp.async.wait_group<2>, prefetch distance 3.
// (G1 previously ran NST=2/PD=1 -> ~2600 cyc exposed latency per chunk; G2's
// deep pipeline shows ~660.) Arithmetic order per accumulator unchanged.
// ============================================================================

#define M_ROWS 16384
#define D_DIM  1024
#define F_DIM  4096

#define BM 128
#define BN 128
#define BK 64
#define NTHREADS 256

// ---------------- device scratch ----------------
__device__ __half g_a1hi [(size_t)M_ROWS * D_DIM];
__device__ __half g_a1lo [(size_t)M_ROWS * D_DIM];
__device__ __half g_w1thi[(size_t)F_DIM * D_DIM];
__device__ __half g_w1tlo[(size_t)F_DIM * D_DIM];
__device__ __half g_hbuf [(size_t)M_ROWS * F_DIM];
__device__ __half g_w2thi[(size_t)D_DIM * F_DIM];
__device__ __half g_w2tlo[(size_t)D_DIM * F_DIM];

__device__ float d_pwl_y[33] = {
    -1.2668497e-04f, -3.3156488e-04f, -8.1420185e-04f, -1.8753475e-03f,
    -4.0496940e-03f, -8.1943491e-03f, -1.5524163e-02f, -2.7505064e-02f,
    -4.5500264e-02f, -7.0103525e-02f, -1.0021080e-01f, -1.3206222e-01f,
    -1.5865525e-01f, -1.6997051e-01f, -1.5426877e-01f, -1.0032342e-01f,
     0.0000000e+00f,  1.4967658e-01f,  3.4573123e-01f,  5.8002949e-01f,
     8.4134475e-01f,  1.1179378e+00f,  1.3997892e+00f,  1.6798965e+00f,
     1.9544997e+00f,  2.2224949e+00f,  2.4844758e+00f,  2.7418056e+00f,
     2.9959503e+00f,  3.2481247e+00f,  3.4991858e+00f,  3.7496684e+00f,
     3.9998733e+00f
};

// ---------------- asm helpers ----------------
__device__ __forceinline__ uint32_t smem_u32(const void* p) {
    uint32_t a;
    asm("{ .reg .u64 t; cvta.to.shared.u64 t, %1; cvt.u32.u64 %0, t; }" : "=r"(a) : "l"(p));
    return a;
}
#define CP16(smem, gmem) \
    asm volatile("cp.async.cg.shared.global [%0], [%1], 16;" :: "r"(smem), "l"(gmem))
#define CP_COMMIT() asm volatile("cp.async.commit_group;" ::: "memory")
template<int N>
__device__ __forceinline__ void cp_wait() {
    asm volatile("cp.async.wait_group %0;" :: "n"(N) : "memory");
}

__device__ __forceinline__ void ldsm4(uint32_t* r, uint32_t addr) {
    asm volatile("ldmatrix.sync.aligned.m8n8.x4.shared.b16 {%0,%1,%2,%3}, [%4];"
        : "=r"(r[0]), "=r"(r[1]), "=r"(r[2]), "=r"(r[3]) : "r"(addr));
}
// c += a*b, f32 accumulator (in-place)
__device__ __forceinline__ void mma16816(float* c, const uint32_t* a, uint32_t b0, uint32_t b1) {
    asm volatile("mma.sync.aligned.m16n8k16.row.col.f32.f16.f16.f32 "
        "{%0,%1,%2,%3},{%4,%5,%6,%7},{%8,%9},{%0,%1,%2,%3};"
        : "+f"(c[0]), "+f"(c[1]), "+f"(c[2]), "+f"(c[3])
        : "r"(a[0]), "r"(a[1]), "r"(a[2]), "r"(a[3]), "r"(b0), "r"(b1));
}
// d = a*b + 0, f32 accum (fresh chain start)
__device__ __forceinline__ void mma16816_z(float* d, const uint32_t* a, uint32_t b0, uint32_t b1) {
    asm volatile("mma.sync.aligned.m16n8k16.row.col.f32.f16.f16.f32 "
        "{%0,%1,%2,%3},{%4,%5,%6,%7},{%8,%9},{%10,%10,%10,%10};"
        : "=f"(d[0]), "=f"(d[1]), "=f"(d[2]), "=f"(d[3])
        : "r"(a[0]), "r"(a[1]), "r"(a[2]), "r"(a[3]), "r"(b0), "r"(b1), "f"(0.0f));
}
// c += a*b, f16 accumulator (2 b32 regs hold 4 halves)
__device__ __forceinline__ void mma16816_h(uint32_t* c, const uint32_t* a, uint32_t b0, uint32_t b1) {
    asm volatile("mma.sync.aligned.m16n8k16.row.col.f16.f16.f16.f16 "
        "{%0,%1},{%2,%3,%4,%5},{%6,%7},{%0,%1};"
        : "+r"(c[0]), "+r"(c[1])
        : "r"(a[0]), "r"(a[1]), "r"(a[2]), "r"(a[3]), "r"(b0), "r"(b1));
}
#define SWZ(o) ((o) ^ (((o) >> 3) & 0x70))

__device__ __forceinline__ float q8(float v) { return rintf(v * 256.0f) * 0.00390625f; }

__device__ __forceinline__ float gelu_pwl(float v, const float* Ys) {
    if (v > 4.0f) return v;
    if (v < -4.0f) return 0.0f;
    float u = (v + 4.0f) * 4.0f;      // exact on q8 grid
    int idx = (int)u; if (idx > 31) idx = 31;
    float f = u - (float)idx;
    float y0 = Ys[idx], y1 = Ys[idx + 1];
    return fmaf(f, y1 - y0, y0);
}

// ---------------- prepass ----------------
__device__ __forceinline__ void split1(float x, __half& h, __half& l) {
    h = __float2half_rn(x);
    l = __float2half_rn((x - __half2float(h)) * 2048.0f);
}
__global__ void split_x_kernel(const float4* __restrict__ in, __half* __restrict__ hi,
                               __half* __restrict__ lo, int n4) {
    int i = blockIdx.x * blockDim.x + threadIdx.x;
    if (i >= n4) return;
    float4 v = in[i];
    __half h[4], l[4];
    split1(v.x, h[0], l[0]); split1(v.y, h[1], l[1]);
    split1(v.z, h[2], l[2]); split1(v.w, h[3], l[3]);
    *(uint2*)(hi + (size_t)i * 4) = *(uint2*)h;
    *(uint2*)(lo + (size_t)i * 4) = *(uint2*)l;
}
// in: [R, C] f32 -> hi/lo: [C, R] fp16 (transpose + split)
__global__ void transpose_split_kernel(const float* __restrict__ in, __half* __restrict__ hi,
                                       __half* __restrict__ lo, int R, int C) {
    __shared__ float t[32][33];
    int c0 = blockIdx.x * 32, r0 = blockIdx.y * 32;
    int tx = threadIdx.x, ty = threadIdx.y;   // 32 x 8
    #pragma unroll
    for (int i = 0; i < 32; i += 8)
        t[ty + i][tx] = in[(size_t)(r0 + ty + i) * C + c0 + tx];
    __syncthreads();
    #pragma unroll
    for (int i = 0; i < 32; i += 8) {
        __half h, l; split1(t[tx][ty + i], h, l);
        size_t o = (size_t)(c0 + ty + i) * R + r0 + tx;
        hi[o] = h; lo[o] = l;
    }
}

// ---------------- main GEMM ----------------
// C[M,N] = A[M,K] @ B[N,K]^T (+bias, q8, optional PWL-GELU)
// 8 warps in 2x4 grid, warp tile 64x32.
// CH16=true  (GEMM1): chain-16 main flushed to SMEM masters; HALF-CHUNK
//                     segmented pipeline (2 buffers x 2 halves, PD=3).
// CH16=false (GEMM2): plain full-K chain; classic NST-stage chunk pipeline.
template<bool HAS_ALO, bool GELU, bool CH16, int NST>
__global__ void __launch_bounds__(NTHREADS, 1)
gemm_mma(const __half* __restrict__ A, const __half* __restrict__ Alo,
         const __half* __restrict__ B, const __half* __restrict__ Blo,
         const float* __restrict__ bias,
         __half* __restrict__ outH, float* __restrict__ outF,
         int K, int N)
{
    constexpr int OFF_ALO = 16384;
    constexpr int OFF_BHI = HAS_ALO ? 32768 : 16384;
    constexpr int OFF_BLO = OFF_BHI + 16384;
    constexpr int SBYTES  = HAS_ALO ? 65536 : 49152;
    constexpr int PD      = NST - 1;          // prefetch distance (chunk path)

    extern __shared__ char smem[];
    const uint32_t sb = smem_u32(smem);
    float* mst = (float*)(smem + NST * SBYTES);   // masters (CH16 only)
    __shared__ float Ys[33];

    const int tid = threadIdx.x;
    const int wid = tid >> 5, l = tid & 31;
    const int mTile = blockIdx.y * BM, nTile = blockIdx.x * BN;
    const int warpM = wid & 1, warpN = wid >> 1;   // 2x4 warp grid
    const int m0 = warpM * 64, n0 = warpN * 32;
    const int nK = K / BK;

    if (GELU && tid < 33) Ys[tid] = d_pwl_y[tid];

    if (CH16) {
        #pragma unroll
        for (int j = 0; j < 64; j++) mst[j * NTHREADS + tid] = 0.0f;
    }

    // ---- ldmatrix address precompute ----
    const uint32_t rx = (uint32_t)((l & 7) << 4);
    uint32_t kpA[4], kpB[4];
    #pragma unroll
    for (int ks = 0; ks < 4; ks++) {
        kpA[ks] = ((uint32_t)(ks * 32 + ((l >> 4) << 4))) ^ rx;
        kpB[ks] = ((uint32_t)(ks * 32 + (((l >> 3) & 1) << 4))) ^ rx;
    }
    uint32_t aoff[4], boff[2];
    #pragma unroll
    for (int mt = 0; mt < 4; mt++) aoff[mt] = (uint32_t)((m0 + mt * 16 + (l & 15)) * 128);
    #pragma unroll
    for (int p = 0; p < 2; p++)
        boff[p] = (uint32_t)((n0 + p * 16 + ((l >> 4) << 3) + (l & 7)) * 128);

    float    cm[4][4][4];    // main f32 (chain or full accumulator)
    uint32_t accx[4][4][2];  // cross (x2048) in f16 accumulators
    #pragma unroll
    for (int mt = 0; mt < 4; mt++)
        #pragma unroll
        for (int t = 0; t < 4; t++) {
            if (!CH16) {
                #pragma unroll
                for (int j = 0; j < 4; j++) cm[mt][t][j] = 0.0f;
            }
            accx[mt][t][0] = 0u; accx[mt][t][1] = 0u;
        }

    // ---- full-chunk loader (G2 path; 16B x 4 per thread per matrix) ----
    auto load_stage = [&](int kt, int s) {
        const uint32_t sbase = sb + s * SBYTES;
        const int k0 = kt * BK;
        #pragma unroll
        for (int i = 0; i < 4; i++) {
            int c = tid + i * NTHREADS;
            int r = c >> 3, cc = c & 7;
            uint32_t so = SWZ((uint32_t)(r * 128 + cc * 16));
            const __half* gA = A + (size_t)(mTile + r) * K + k0 + cc * 8;
            CP16(sbase + so, gA);
            if (HAS_ALO) {
                const __half* gAl = Alo + (size_t)(mTile + r) * K + k0 + cc * 8;
                CP16(sbase + OFF_ALO + so, gAl);
            }
            const __half* gB  = B   + (size_t)(nTile + r) * K + k0 + cc * 8;
            const __half* gBl = Blo + (size_t)(nTile + r) * K + k0 + cc * 8;
            CP16(sbase + OFF_BHI + so, gB);
            CP16(sbase + OFF_BLO + so, gBl);
        }
    };

    // ---- half-chunk loader (G1 path): seg = (chunk, half) ----
    // Loads the byte-set of k-halves; SWZ scatters within the 128B row but
    // loader and ldmatrix compute identical swizzled addresses.
    auto load_seg = [&](int seg) {
        const int kt = seg >> 1, h = seg & 1;
        const uint32_t sbase = sb + ((kt & 1) * SBYTES);
        const int k0 = kt * BK;
        #pragma unroll
        for (int i = 0; i < 2; i++) {
            int c = tid + i * NTHREADS;          // 0..511
            int r = c >> 2, cc = (c & 3) + h * 4;
            uint32_t so = SWZ((uint32_t)(r * 128 + cc * 16));
            const __half* gA = A + (size_t)(mTile + r) * K + k0 + cc * 8;
            CP16(sbase + so, gA);
            const __half* gAl = Alo + (size_t)(mTile + r) * K + k0 + cc * 8;
            CP16(sbase + OFF_ALO + so, gAl);
            const __half* gB  = B   + (size_t)(nTile + r) * K + k0 + cc * 8;
            const __half* gBl = Blo + (size_t)(nTile + r) * K + k0 + cc * 8;
            CP16(sbase + OFF_BHI + so, gB);
            CP16(sbase + OFF_BLO + so, gBl);
        }
    };

    // ---- MMA work for one ks-step ----
    auto do_ks = [&](uint32_t st, int ks, bool z) {
        uint32_t ah[4][4], al[4][4];
        uint32_t bh[2][4], bl[2][4];
        #pragma unroll
        for (int p = 0; p < 2; p++) {
            ldsm4(bh[p], st + OFF_BHI + boff[p] + kpB[ks]);
            ldsm4(bl[p], st + OFF_BLO + boff[p] + kpB[ks]);
        }
        #pragma unroll
        for (int mt = 0; mt < 4; mt++) {
            ldsm4(ah[mt], st + aoff[mt] + kpA[ks]);
            if (HAS_ALO) ldsm4(al[mt], st + OFF_ALO + aoff[mt] + kpA[ks]);
        }
        #pragma unroll
        for (int p = 0; p < 2; p++)
            #pragma unroll
            for (int tt = 0; tt < 2; tt++) {
                const int t = p * 2 + tt;
                const uint32_t h0 = bh[p][tt * 2], h1 = bh[p][tt * 2 + 1];
                const uint32_t l0 = bl[p][tt * 2], l1 = bl[p][tt * 2 + 1];
                #pragma unroll
                for (int mt = 0; mt < 4; mt++) {
                    if (z) mma16816_z(cm[mt][t], ah[mt], h0, h1);
                    else   mma16816  (cm[mt][t], ah[mt], h0, h1);
                    mma16816_h(accx[mt][t], ah[mt], l0, l1);
                    if (HAS_ALO) mma16816_h(accx[mt][t], al[mt], h0, h1);
                }
            }
    };

    if (CH16) {
        // ---- G1: segmented half-chunk pipeline, 4 segs in flight ----
        const int nSeg = nK * 2;
        load_seg(0); CP_COMMIT();
        load_seg(1); CP_COMMIT();
        load_seg(2); CP_COMMIT();
        for (int s = 0; s < nSeg; s++) {
            cp_wait<2>();
            __syncthreads();
            if (s + 3 < nSeg) load_seg(s + 3);
            CP_COMMIT();
            const uint32_t st = sb + (((s >> 1) & 1) * SBYTES);
            const int h = s & 1;
            do_ks(st, h * 2 + 0, (s % 8) == 0);
            do_ks(st, h * 2 + 1, false);
            if ((s & 7) == 7) {
                // RN flush of the chain-16 group into SMEM masters
                #pragma unroll
                for (int mt = 0; mt < 4; mt++)
                    #pragma unroll
                    for (int t = 0; t < 4; t++)
                        #pragma unroll
                        for (int j = 0; j < 4; j++) {
                            const int idx = (mt * 4 + t) * 4 + j;
                            mst[idx * NTHREADS + tid] += cm[mt][t][j];
                        }
            }
        }
    } else {
        // ---- G2: classic full-chunk pipeline ----
        #pragma unroll
        for (int i = 0; i < PD; i++) { load_stage(i, i); CP_COMMIT(); }
        for (int kt = 0; kt < nK; kt++) {
            cp_wait<PD - 1>();
            __syncthreads();
            if (kt + PD < nK) load_stage(kt + PD, (kt + PD) % NST);
            CP_COMMIT();
            const uint32_t st = sb + (kt % NST) * SBYTES;
            #pragma unroll
            for (int ks = 0; ks < 4; ks++) do_ks(st, ks, false);
        }
    }

    // ---- epilogue: v = main + cross_f16/2048 + bias ----
    const float invS = 4.8828125e-4f;   // 1/2048
    const int rg = mTile + m0 + (l >> 2);
    const int cg = nTile + n0 + (l & 3) * 2;
    #pragma unroll
    for (int mt = 0; mt < 4; mt++) {
        const int r0r = rg + mt * 16;
        #pragma unroll
        for (int t = 0; t < 4; t++) {
            const int col = cg + t * 8;
            const float b0 = __ldg(bias + col), b1 = __ldg(bias + col + 1);
            const __half2 c01 = *(const __half2*)&accx[mt][t][0];
            const __half2 c23 = *(const __half2*)&accx[mt][t][1];
            float m0v, m1v, m2v, m3v;
            if (CH16) {
                const int ib = (mt * 4 + t) * 4;
                m0v = mst[(ib + 0) * NTHREADS + tid];
                m1v = mst[(ib + 1) * NTHREADS + tid];
                m2v = mst[(ib + 2) * NTHREADS + tid];
                m3v = mst[(ib + 3) * NTHREADS + tid];
            } else {
                m0v = cm[mt][t][0]; m1v = cm[mt][t][1];
                m2v = cm[mt][t][2]; m3v = cm[mt][t][3];
            }
            float v0 = fmaf(__half2float(__low2half(c01)),  invS, m0v) + b0;
            float v1 = fmaf(__half2float(__high2half(c01)), invS, m1v) + b1;
            float v2 = fmaf(__half2float(__low2half(c23)),  invS, m2v) + b0;
            float v3 = fmaf(__half2float(__high2half(c23)), invS, m3v) + b1;
            if (GELU) {
                v0 = q8(gelu_pwl(q8(v0), Ys)); v1 = q8(gelu_pwl(q8(v1), Ys));
                v2 = q8(gelu_pwl(q8(v2), Ys)); v3 = q8(gelu_pwl(q8(v3), Ys));
                *(__half2*)(outH + (size_t)r0r * N + col) =
                    __halves2half2(__float2half_rn(v0), __float2half_rn(v1));
                *(__half2*)(outH + (size_t)(r0r + 8) * N + col) =
                    __halves2half2(__float2half_rn(v2), __float2half_rn(v3));
            } else {
                float2 o0 = {q8(v0), q8(v1)}, o1 = {q8(v2), q8(v3)};
                *(float2*)(outF + (size_t)r0r * N + col) = o0;
                *(float2*)(outF + (size_t)(r0r + 8) * N + col) = o1;
            }
        }
    }
}

extern "C" void kernel_launch(void* const* d_in, const int* in_sizes, int n_in,
                              void* d_out, int out_size)
{
    const float* x  = (const float*)d_in[0];
    const float* w1 = (const float*)d_in[1];
    const float* b1 = (const float*)d_in[2];
    const float* w2 = (const float*)d_in[3];
    const float* b2 = (const float*)d_in[4];
    float* out = (float*)d_out;

    __half *a1hi, *a1lo, *w1thi, *w1tlo, *hbuf, *w2thi, *w2tlo;
    cudaGetSymbolAddress((void**)&a1hi, g_a1hi);
    cudaGetSymbolAddress((void**)&a1lo, g_a1lo);
    cudaGetSymbolAddress((void**)&w1thi, g_w1thi);
    cudaGetSymbolAddress((void**)&w1tlo, g_w1tlo);
    cudaGetSymbolAddress((void**)&hbuf, g_hbuf);
    cudaGetSymbolAddress((void**)&w2thi, g_w2thi);
    cudaGetSymbolAddress((void**)&w2tlo, g_w2tlo);

    int n4 = M_ROWS * D_DIM / 4;
    split_x_kernel<<<(n4 + 255) / 256, 256>>>((const float4*)x, a1hi, a1lo, n4);
    transpose_split_kernel<<<dim3(F_DIM / 32, D_DIM / 32), dim3(32, 8)>>>(w1, w1thi, w1tlo, D_DIM, F_DIM);
    transpose_split_kernel<<<dim3(D_DIM / 32, F_DIM / 32), dim3(32, 8)>>>(w2, w2thi, w2tlo, F_DIM, D_DIM);

    constexpr int SMEM1 = 2 * 65536 + 65536;   // 2 buffers + masters = 192 KB
    constexpr int SMEM2 = 4 * 49152;           // 4 stages          = 192 KB
    cudaFuncSetAttribute((const void*)gemm_mma<true,  true,  true,  2>,
                         cudaFuncAttributeMaxDynamicSharedMemorySize, SMEM1);
    cudaFuncSetAttribute((const void*)gemm_mma<false, false, false, 4>,
                         cudaFuncAttributeMaxDynamicSharedMemorySize, SMEM2);

    // GEMM1: [16384,1024] x [4096,1024]^T -> h (gelu+q8, fp16); segmented pipe
    gemm_mma<true, true, true, 2><<<dim3(F_DIM / BN, M_ROWS / BM), NTHREADS, SMEM1>>>(
        a1hi, a1lo, w1thi, w1tlo, b1, hbuf, nullptr, D_DIM, F_DIM);
    // GEMM2: [16384,4096] x [1024,4096]^T -> out (q8, f32); plain chains
    gemm_mma<false, false, false, 4><<<dim3(D_DIM / BN, M_ROWS / BM), NTHREADS, SMEM2>>>(
        hbuf, hbuf, w2thi, w2tlo, b2, nullptr, out, F_DIM, D_DIM);
}

// round 15
// speedup vs baseline: 1.1644x; 1.1644x over previous
#include <cuda_runtime.h>
#include <cuda_fp16.h>
#include <cstdint>
#include <cstddef>
#include <type_traits>

// ============================================================================
// Quantized FFN via fp16-split warp-level mma.sync (HMMA) GEMMs.
//   GEMM1: h = q8(gelu_pwl(q8(x@w1+b1)))  -> h exact on q8 grid, stored fp16
//   GEMM2: out = q8(h@w2+b2)
// Split: hi=fp16(x), lo=fp16((x-hi)*2048).
// GEMM1 main: f32 chains of 16 k-steps flushed to per-thread SMEM masters
//             (R12 pipeline: NST=2, per-chunk sync -- best measured G1).
// GEMM2 main: plain full-K f32 chain; R15: MEGA-STAGES -- 4 slots, 2 chunks
//             per sync (halves barrier-drain count; loads overlap compute).
// Cross terms: f16-accumulator MMAs (x2048).
// ============================================================================

#define M_ROWS 16384
#define D_DIM  1024
#define F_DIM  4096

#define BM 128
#define BN 128
#define BK 64
#define NTHREADS 256

// ---------------- device scratch ----------------
__device__ __half g_a1hi [(size_t)M_ROWS * D_DIM];
__device__ __half g_a1lo [(size_t)M_ROWS * D_DIM];
__device__ __half g_w1thi[(size_t)F_DIM * D_DIM];
__device__ __half g_w1tlo[(size_t)F_DIM * D_DIM];
__device__ __half g_hbuf [(size_t)M_ROWS * F_DIM];
__device__ __half g_w2thi[(size_t)D_DIM * F_DIM];
__device__ __half g_w2tlo[(size_t)D_DIM * F_DIM];

__device__ float d_pwl_y[33] = {
    -1.2668497e-04f, -3.3156488e-04f, -8.1420185e-04f, -1.8753475e-03f,
    -4.0496940e-03f, -8.1943491e-03f, -1.5524163e-02f, -2.7505064e-02f,
    -4.5500264e-02f, -7.0103525e-02f, -1.0021080e-01f, -1.3206222e-01f,
    -1.5865525e-01f, -1.6997051e-01f, -1.5426877e-01f, -1.0032342e-01f,
     0.0000000e+00f,  1.4967658e-01f,  3.4573123e-01f,  5.8002949e-01f,
     8.4134475e-01f,  1.1179378e+00f,  1.3997892e+00f,  1.6798965e+00f,
     1.9544997e+00f,  2.2224949e+00f,  2.4844758e+00f,  2.7418056e+00f,
     2.9959503e+00f,  3.2481247e+00f,  3.4991858e+00f,  3.7496684e+00f,
     3.9998733e+00f
};

// ---------------- asm helpers ----------------
__device__ __forceinline__ uint32_t smem_u32(const void* p) {
    uint32_t a;
    asm("{ .reg .u64 t; cvta.to.shared.u64 t, %1; cvt.u32.u64 %0, t; }" : "=r"(a) : "l"(p));
    return a;
}
#define CP16(smem, gmem) \
    asm volatile("cp.async.cg.shared.global [%0], [%1], 16;" :: "r"(smem), "l"(gmem))
#define CP_COMMIT() asm volatile("cp.async.commit_group;" ::: "memory")
template<int N>
__device__ __forceinline__ void cp_wait() {
    asm volatile("cp.async.wait_group %0;" :: "n"(N) : "memory");
}

__device__ __forceinline__ void ldsm4(uint32_t* r, uint32_t addr) {
    asm volatile("ldmatrix.sync.aligned.m8n8.x4.shared.b16 {%0,%1,%2,%3}, [%4];"
        : "=r"(r[0]), "=r"(r[1]), "=r"(r[2]), "=r"(r[3]) : "r"(addr));
}
// c += a*b, f32 accumulator (in-place)
__device__ __forceinline__ void mma16816(float* c, const uint32_t* a, uint32_t b0, uint32_t b1) {
    asm volatile("mma.sync.aligned.m16n8k16.row.col.f32.f16.f16.f32 "
        "{%0,%1,%2,%3},{%4,%5,%6,%7},{%8,%9},{%0,%1,%2,%3};"
        : "+f"(c[0]), "+f"(c[1]), "+f"(c[2]), "+f"(c[3])
        : "r"(a[0]), "r"(a[1]), "r"(a[2]), "r"(a[3]), "r"(b0), "r"(b1));
}
// d = a*b + 0, f32 accum (fresh chain start)
__device__ __forceinline__ void mma16816_z(float* d, const uint32_t* a, uint32_t b0, uint32_t b1) {
    asm volatile("mma.sync.aligned.m16n8k16.row.col.f32.f16.f16.f32 "
        "{%0,%1,%2,%3},{%4,%5,%6,%7},{%8,%9},{%10,%10,%10,%10};"
        : "=f"(d[0]), "=f"(d[1]), "=f"(d[2]), "=f"(d[3])
        : "r"(a[0]), "r"(a[1]), "r"(a[2]), "r"(a[3]), "r"(b0), "r"(b1), "f"(0.0f));
}
// c += a*b, f16 accumulator (2 b32 regs hold 4 halves)
__device__ __forceinline__ void mma16816_h(uint32_t* c, const uint32_t* a, uint32_t b0, uint32_t b1) {
    asm volatile("mma.sync.aligned.m16n8k16.row.col.f16.f16.f16.f16 "
        "{%0,%1},{%2,%3,%4,%5},{%6,%7},{%0,%1};"
        : "+r"(c[0]), "+r"(c[1])
        : "r"(a[0]), "r"(a[1]), "r"(a[2]), "r"(a[3]), "r"(b0), "r"(b1));
}
#define SWZ(o) ((o) ^ (((o) >> 3) & 0x70))

__device__ __forceinline__ float q8(float v) { return rintf(v * 256.0f) * 0.00390625f; }

__device__ __forceinline__ float gelu_pwl(float v, const float* Ys) {
    if (v > 4.0f) return v;
    if (v < -4.0f) return 0.0f;
    float u = (v + 4.0f) * 4.0f;      // exact on q8 grid
    int idx = (int)u; if (idx > 31) idx = 31;
    float f = u - (float)idx;
    float y0 = Ys[idx], y1 = Ys[idx + 1];
    return fmaf(f, y1 - y0, y0);
}

// ---------------- prepass ----------------
__device__ __forceinline__ void split1(float x, __half& h, __half& l) {
    h = __float2half_rn(x);
    l = __float2half_rn((x - __half2float(h)) * 2048.0f);
}
__global__ void split_x_kernel(const float4* __restrict__ in, __half* __restrict__ hi,
                               __half* __restrict__ lo, int n4) {
    int i = blockIdx.x * blockDim.x + threadIdx.x;
    if (i >= n4) return;
    float4 v = in[i];
    __half h[4], l[4];
    split1(v.x, h[0], l[0]); split1(v.y, h[1], l[1]);
    split1(v.z, h[2], l[2]); split1(v.w, h[3], l[3]);
    *(uint2*)(hi + (size_t)i * 4) = *(uint2*)h;
    *(uint2*)(lo + (size_t)i * 4) = *(uint2*)l;
}
// in: [R, C] f32 -> hi/lo: [C, R] fp16 (transpose + split)
__global__ void transpose_split_kernel(const float* __restrict__ in, __half* __restrict__ hi,
                                       __half* __restrict__ lo, int R, int C) {
    __shared__ float t[32][33];
    int c0 = blockIdx.x * 32, r0 = blockIdx.y * 32;
    int tx = threadIdx.x, ty = threadIdx.y;   // 32 x 8
    #pragma unroll
    for (int i = 0; i < 32; i += 8)
        t[ty + i][tx] = in[(size_t)(r0 + ty + i) * C + c0 + tx];
    __syncthreads();
    #pragma unroll
    for (int i = 0; i < 32; i += 8) {
        __half h, l; split1(t[tx][ty + i], h, l);
        size_t o = (size_t)(c0 + ty + i) * R + r0 + tx;
        hi[o] = h; lo[o] = l;
    }
}

// ---------------- main GEMM ----------------
// C[M,N] = A[M,K] @ B[N,K]^T (+bias, q8, optional PWL-GELU)
// 8 warps in 2x4 grid, warp tile 64x32.
// CH16=true  (GEMM1): chain-16 main -> SMEM masters; NST=2 per-chunk pipe.
// CH16=false (GEMM2): plain full-K chain; 4-slot mega-stage pipe (2 chunks/sync).
template<bool HAS_ALO, bool GELU, bool CH16, int NST>
__global__ void __launch_bounds__(NTHREADS, 1)
gemm_mma(const __half* __restrict__ A, const __half* __restrict__ Alo,
         const __half* __restrict__ B, const __half* __restrict__ Blo,
         const float* __restrict__ bias,
         __half* __restrict__ outH, float* __restrict__ outF,
         int K, int N)
{
    constexpr int OFF_ALO = 16384;
    constexpr int OFF_BHI = HAS_ALO ? 32768 : 16384;
    constexpr int OFF_BLO = OFF_BHI + 16384;
    constexpr int SBYTES  = HAS_ALO ? 65536 : 49152;

    extern __shared__ char smem[];
    const uint32_t sb = smem_u32(smem);
    float* mst = (float*)(smem + NST * SBYTES);   // masters (CH16 only)
    __shared__ float Ys[33];

    const int tid = threadIdx.x;
    const int wid = tid >> 5, l = tid & 31;
    const int mTile = blockIdx.y * BM, nTile = blockIdx.x * BN;
    const int warpM = wid & 1, warpN = wid >> 1;   // 2x4 warp grid
    const int m0 = warpM * 64, n0 = warpN * 32;
    const int nK = K / BK;

    if (GELU && tid < 33) Ys[tid] = d_pwl_y[tid];

    if (CH16) {
        #pragma unroll
        for (int j = 0; j < 64; j++) mst[j * NTHREADS + tid] = 0.0f;
    }

    // ---- ldmatrix address precompute ----
    const uint32_t rx = (uint32_t)((l & 7) << 4);
    uint32_t kpA[4], kpB[4];
    #pragma unroll
    for (int ks = 0; ks < 4; ks++) {
        kpA[ks] = ((uint32_t)(ks * 32 + ((l >> 4) << 4))) ^ rx;
        kpB[ks] = ((uint32_t)(ks * 32 + (((l >> 3) & 1) << 4))) ^ rx;
    }
    uint32_t aoff[4], boff[2];
    #pragma unroll
    for (int mt = 0; mt < 4; mt++) aoff[mt] = (uint32_t)((m0 + mt * 16 + (l & 15)) * 128);
    #pragma unroll
    for (int p = 0; p < 2; p++)
        boff[p] = (uint32_t)((n0 + p * 16 + ((l >> 4) << 3) + (l & 7)) * 128);

    float    cm[4][4][4];    // main f32 (chain or full accumulator)
    uint32_t accx[4][4][2];  // cross (x2048) in f16 accumulators
    #pragma unroll
    for (int mt = 0; mt < 4; mt++)
        #pragma unroll
        for (int t = 0; t < 4; t++) {
            if (!CH16) {
                #pragma unroll
                for (int j = 0; j < 4; j++) cm[mt][t][j] = 0.0f;
            }
            accx[mt][t][0] = 0u; accx[mt][t][1] = 0u;
        }

    // ---- full-chunk loader (16B x 4 per thread per matrix) ----
    auto load_stage = [&](int kt, int s) {
        const uint32_t sbase = sb + s * SBYTES;
        const int k0 = kt * BK;
        #pragma unroll
        for (int i = 0; i < 4; i++) {
            int c = tid + i * NTHREADS;
            int r = c >> 3, cc = c & 7;
            uint32_t so = SWZ((uint32_t)(r * 128 + cc * 16));
            const __half* gA = A + (size_t)(mTile + r) * K + k0 + cc * 8;
            CP16(sbase + so, gA);
            if (HAS_ALO) {
                const __half* gAl = Alo + (size_t)(mTile + r) * K + k0 + cc * 8;
                CP16(sbase + OFF_ALO + so, gAl);
            }
            const __half* gB  = B   + (size_t)(nTile + r) * K + k0 + cc * 8;
            const __half* gBl = Blo + (size_t)(nTile + r) * K + k0 + cc * 8;
            CP16(sbase + OFF_BHI + so, gB);
            CP16(sbase + OFF_BLO + so, gBl);
        }
    };

    // ---- MMA work for one ks-step ----
    auto do_ks = [&](uint32_t st, int ks, bool z) {
        uint32_t ah[4][4], al[4][4];
        uint32_t bh[2][4], bl[2][4];
        #pragma unroll
        for (int p = 0; p < 2; p++) {
            ldsm4(bh[p], st + OFF_BHI + boff[p] + kpB[ks]);
            ldsm4(bl[p], st + OFF_BLO + boff[p] + kpB[ks]);
        }
        #pragma unroll
        for (int mt = 0; mt < 4; mt++) {
            ldsm4(ah[mt], st + aoff[mt] + kpA[ks]);
            if (HAS_ALO) ldsm4(al[mt], st + OFF_ALO + aoff[mt] + kpA[ks]);
        }
        #pragma unroll
        for (int p = 0; p < 2; p++)
            #pragma unroll
            for (int tt = 0; tt < 2; tt++) {
                const int t = p * 2 + tt;
                const uint32_t h0 = bh[p][tt * 2], h1 = bh[p][tt * 2 + 1];
                const uint32_t l0 = bl[p][tt * 2], l1 = bl[p][tt * 2 + 1];
                #pragma unroll
                for (int mt = 0; mt < 4; mt++) {
                    if (z) mma16816_z(cm[mt][t], ah[mt], h0, h1);
                    else   mma16816  (cm[mt][t], ah[mt], h0, h1);
                    mma16816_h(accx[mt][t], ah[mt], l0, l1);
                    if (HAS_ALO) mma16816_h(accx[mt][t], al[mt], h0, h1);
                }
            }
    };

    if (CH16) {
        // ---- G1: R12 pipeline (NST=2, per-chunk sync), chain-16 masters ----
        load_stage(0, 0); CP_COMMIT();
        for (int kt = 0; kt < nK; kt++) {
            cp_wait<0>();
            __syncthreads();
            if (kt + 1 < nK) load_stage(kt + 1, (kt + 1) & 1);
            CP_COMMIT();
            const uint32_t st = sb + (kt & 1) * SBYTES;
            do_ks(st, 0, (kt & 3) == 0);
            do_ks(st, 1, false);
            do_ks(st, 2, false);
            do_ks(st, 3, false);
            if ((kt & 3) == 3) {
                // RN flush of the chain-16 group into SMEM masters
                #pragma unroll
                for (int mt = 0; mt < 4; mt++)
                    #pragma unroll
                    for (int t = 0; t < 4; t++)
                        #pragma unroll
                        for (int j = 0; j < 4; j++) {
                            const int idx = (mt * 4 + t) * 4 + j;
                            mst[idx * NTHREADS + tid] += cm[mt][t][j];
                        }
            }
        }
    } else {
        // ---- G2: mega-stage pipeline: 4 slots, 2 chunks per sync ----
        load_stage(0, 0); CP_COMMIT();
        load_stage(1, 1); CP_COMMIT();
        for (int kp = 0; kp < nK; kp += 2) {
            cp_wait<0>();
            __syncthreads();
            // prefetch next pair into the slots freed by the PREVIOUS iter
            if (kp + 2 < nK) { load_stage(kp + 2, (kp + 2) & 3); CP_COMMIT(); }
            if (kp + 3 < nK) { load_stage(kp + 3, (kp + 3) & 3); CP_COMMIT(); }
            const uint32_t st0 = sb + (kp & 3) * SBYTES;
            const uint32_t st1 = sb + ((kp + 1) & 3) * SBYTES;
            #pragma unroll
            for (int ks = 0; ks < 4; ks++) do_ks(st0, ks, false);
            #pragma unroll
            for (int ks = 0; ks < 4; ks++) do_ks(st1, ks, false);
        }
    }

    // ---- epilogue: v = main + cross_f16/2048 + bias ----
    const float invS = 4.8828125e-4f;   // 1/2048
    const int rg = mTile + m0 + (l >> 2);
    const int cg = nTile + n0 + (l & 3) * 2;
    #pragma unroll
    for (int mt = 0; mt < 4; mt++) {
        const int r0r = rg + mt * 16;
        #pragma unroll
        for (int t = 0; t < 4; t++) {
            const int col = cg + t * 8;
            const float b0 = __ldg(bias + col), b1 = __ldg(bias + col + 1);
            const __half2 c01 = *(const __half2*)&accx[mt][t][0];
            const __half2 c23 = *(const __half2*)&accx[mt][t][1];
            float m0v, m1v, m2v, m3v;
            if (CH16) {
                const int ib = (mt * 4 + t) * 4;
                m0v = mst[(ib + 0) * NTHREADS + tid];
                m1v = mst[(ib + 1) * NTHREADS + tid];
                m2v = mst[(ib + 2) * NTHREADS + tid];
                m3v = mst[(ib + 3) * NTHREADS + tid];
            } else {
                m0v = cm[mt][t][0]; m1v = cm[mt][t][1];
                m2v = cm[mt][t][2]; m3v = cm[mt][t][3];
            }
            float v0 = fmaf(__half2float(__low2half(c01)),  invS, m0v) + b0;
            float v1 = fmaf(__half2float(__high2half(c01)), invS, m1v) + b1;
            float v2 = fmaf(__half2float(__low2half(c23)),  invS, m2v) + b0;
            float v3 = fmaf(__half2float(__high2half(c23)), invS, m3v) + b1;
            if (GELU) {
                v0 = q8(gelu_pwl(q8(v0), Ys)); v1 = q8(gelu_pwl(q8(v1), Ys));
                v2 = q8(gelu_pwl(q8(v2), Ys)); v3 = q8(gelu_pwl(q8(v3), Ys));
                *(__half2*)(outH + (size_t)r0r * N + col) =
                    __halves2half2(__float2half_rn(v0), __float2half_rn(v1));
                *(__half2*)(outH + (size_t)(r0r + 8) * N + col) =
                    __halves2half2(__float2half_rn(v2), __float2half_rn(v3));
            } else {
                float2 o0 = {q8(v0), q8(v1)}, o1 = {q8(v2), q8(v3)};
                *(float2*)(outF + (size_t)r0r * N + col) = o0;
                *(float2*)(outF + (size_t)(r0r + 8) * N + col) = o1;
            }
        }
    }
}

extern "C" void kernel_launch(void* const* d_in, const int* in_sizes, int n_in,
                              void* d_out, int out_size)
{
    const float* x  = (const float*)d_in[0];
    const float* w1 = (const float*)d_in[1];
    const float* b1 = (const float*)d_in[2];
    const float* w2 = (const float*)d_in[3];
    const float* b2 = (const float*)d_in[4];
    float* out = (float*)d_out;

    __half *a1hi, *a1lo, *w1thi, *w1tlo, *hbuf, *w2thi, *w2tlo;
    cudaGetSymbolAddress((void**)&a1hi, g_a1hi);
    cudaGetSymbolAddress((void**)&a1lo, g_a1lo);
    cudaGetSymbolAddress((void**)&w1thi, g_w1thi);
    cudaGetSymbolAddress((void**)&w1tlo, g_w1tlo);
    cudaGetSymbolAddress((void**)&hbuf, g_hbuf);
    cudaGetSymbolAddress((void**)&w2thi, g_w2thi);
    cudaGetSymbolAddress((void**)&w2tlo, g_w2tlo);

    int n4 = M_ROWS * D_DIM / 4;
    split_x_kernel<<<(n4 + 255) / 256, 256>>>((const float4*)x, a1hi, a1lo, n4);
    transpose_split_kernel<<<dim3(F_DIM / 32, D_DIM / 32), dim3(32, 8)>>>(w1, w1thi, w1tlo, D_DIM, F_DIM);
    transpose_split_kernel<<<dim3(D_DIM / 32, F_DIM / 32), dim3(32, 8)>>>(w2, w2thi, w2tlo, F_DIM, D_DIM);

    constexpr int SMEM1 = 2 * 65536 + 65536;   // 2 stages + masters = 192 KB
    constexpr int SMEM2 = 4 * 49152;           // 4 slots           = 192 KB
    cudaFuncSetAttribute((const void*)gemm_mma<true,  true,  true,  2>,
                         cudaFuncAttributeMaxDynamicSharedMemorySize, SMEM1);
    cudaFuncSetAttribute((const void*)gemm_mma<false, false, false, 4>,
                         cudaFuncAttributeMaxDynamicSharedMemorySize, SMEM2);

    // GEMM1: [16384,1024] x [4096,1024]^T -> h (gelu+q8, fp16); chain-16 masters
    gemm_mma<true, true, true, 2><<<dim3(F_DIM / BN, M_ROWS / BM), NTHREADS, SMEM1>>>(
        a1hi, a1lo, w1thi, w1tlo, b1, hbuf, nullptr, D_DIM, F_DIM);
    // GEMM2: [16384,4096] x [1024,4096]^T -> out (q8, f32); mega-stage pipe
    gemm_mma<false, false, false, 4><<<dim3(D_DIM / BN, M_ROWS / BM), NTHREADS, SMEM2>>>(
        hbuf, hbuf, w2thi, w2tlo, b2, nullptr, out, F_DIM, D_DIM);
}

// round 16
// speedup vs baseline: 1.2094x; 1.0387x over previous
#include <cuda_runtime.h>
#include <cuda_fp16.h>
#include <cstdint>
#include <cstddef>
#include <type_traits>

// ============================================================================
// Quantized FFN via fp16-split warp-level mma.sync (HMMA) GEMMs.
//   GEMM1: h = q8(gelu_pwl(q8(x@w1+b1)))  -> h exact on q8 grid, stored fp16
//   GEMM2: out = q8(h@w2+b2)
// Split: hi=fp16(x), lo=fp16((x-hi)*2048).
// GEMM1 main: f32 chains of 16 k-steps flushed to per-thread SMEM masters
//             (R13 pipeline verbatim: NST=2, per-chunk sync; best measured).
// GEMM2 main: plain full-K f32 chain; mega-stage pipe (4 slots, 2 chunks
//             per sync -- halves barrier drains; R15-validated).
// Cross terms: f16-accumulator MMAs (x2048).
// ============================================================================

#define M_ROWS 16384
#define D_DIM  1024
#define F_DIM  4096

#define BM 128
#define BN 128
#define BK 64
#define NTHREADS 256

// ---------------- device scratch ----------------
__device__ __half g_a1hi [(size_t)M_ROWS * D_DIM];
__device__ __half g_a1lo [(size_t)M_ROWS * D_DIM];
__device__ __half g_w1thi[(size_t)F_DIM * D_DIM];
__device__ __half g_w1tlo[(size_t)F_DIM * D_DIM];
__device__ __half g_hbuf [(size_t)M_ROWS * F_DIM];
__device__ __half g_w2thi[(size_t)D_DIM * F_DIM];
__device__ __half g_w2tlo[(size_t)D_DIM * F_DIM];

__device__ float d_pwl_y[33] = {
    -1.2668497e-04f, -3.3156488e-04f, -8.1420185e-04f, -1.8753475e-03f,
    -4.0496940e-03f, -8.1943491e-03f, -1.5524163e-02f, -2.7505064e-02f,
    -4.5500264e-02f, -7.0103525e-02f, -1.0021080e-01f, -1.3206222e-01f,
    -1.5865525e-01f, -1.6997051e-01f, -1.5426877e-01f, -1.0032342e-01f,
     0.0000000e+00f,  1.4967658e-01f,  3.4573123e-01f,  5.8002949e-01f,
     8.4134475e-01f,  1.1179378e+00f,  1.3997892e+00f,  1.6798965e+00f,
     1.9544997e+00f,  2.2224949e+00f,  2.4844758e+00f,  2.7418056e+00f,
     2.9959503e+00f,  3.2481247e+00f,  3.4991858e+00f,  3.7496684e+00f,
     3.9998733e+00f
};

// ---------------- asm helpers ----------------
__device__ __forceinline__ uint32_t smem_u32(const void* p) {
    uint32_t a;
    asm("{ .reg .u64 t; cvta.to.shared.u64 t, %1; cvt.u32.u64 %0, t; }" : "=r"(a) : "l"(p));
    return a;
}
#define CP16(smem, gmem) \
    asm volatile("cp.async.cg.shared.global [%0], [%1], 16;" :: "r"(smem), "l"(gmem))
#define CP_COMMIT() asm volatile("cp.async.commit_group;" ::: "memory")
template<int N>
__device__ __forceinline__ void cp_wait() {
    asm volatile("cp.async.wait_group %0;" :: "n"(N) : "memory");
}

__device__ __forceinline__ void ldsm4(uint32_t* r, uint32_t addr) {
    asm volatile("ldmatrix.sync.aligned.m8n8.x4.shared.b16 {%0,%1,%2,%3}, [%4];"
        : "=r"(r[0]), "=r"(r[1]), "=r"(r[2]), "=r"(r[3]) : "r"(addr));
}
// c += a*b, f32 accumulator (in-place)
__device__ __forceinline__ void mma16816(float* c, const uint32_t* a, uint32_t b0, uint32_t b1) {
    asm volatile("mma.sync.aligned.m16n8k16.row.col.f32.f16.f16.f32 "
        "{%0,%1,%2,%3},{%4,%5,%6,%7},{%8,%9},{%0,%1,%2,%3};"
        : "+f"(c[0]), "+f"(c[1]), "+f"(c[2]), "+f"(c[3])
        : "r"(a[0]), "r"(a[1]), "r"(a[2]), "r"(a[3]), "r"(b0), "r"(b1));
}
// d = a*b + 0, f32 accum (fresh chain start)
__device__ __forceinline__ void mma16816_z(float* d, const uint32_t* a, uint32_t b0, uint32_t b1) {
    asm volatile("mma.sync.aligned.m16n8k16.row.col.f32.f16.f16.f32 "
        "{%0,%1,%2,%3},{%4,%5,%6,%7},{%8,%9},{%10,%10,%10,%10};"
        : "=f"(d[0]), "=f"(d[1]), "=f"(d[2]), "=f"(d[3])
        : "r"(a[0]), "r"(a[1]), "r"(a[2]), "r"(a[3]), "r"(b0), "r"(b1), "f"(0.0f));
}
// c += a*b, f16 accumulator (2 b32 regs hold 4 halves)
__device__ __forceinline__ void mma16816_h(uint32_t* c, const uint32_t* a, uint32_t b0, uint32_t b1) {
    asm volatile("mma.sync.aligned.m16n8k16.row.col.f16.f16.f16.f16 "
        "{%0,%1},{%2,%3,%4,%5},{%6,%7},{%0,%1};"
        : "+r"(c[0]), "+r"(c[1])
        : "r"(a[0]), "r"(a[1]), "r"(a[2]), "r"(a[3]), "r"(b0), "r"(b1));
}
#define SWZ(o) ((o) ^ (((o) >> 3) & 0x70))

__device__ __forceinline__ float q8(float v) { return rintf(v * 256.0f) * 0.00390625f; }

__device__ __forceinline__ float gelu_pwl(float v, const float* Ys) {
    if (v > 4.0f) return v;
    if (v < -4.0f) return 0.0f;
    float u = (v + 4.0f) * 4.0f;      // exact on q8 grid
    int idx = (int)u; if (idx > 31) idx = 31;
    float f = u - (float)idx;
    float y0 = Ys[idx], y1 = Ys[idx + 1];
    return fmaf(f, y1 - y0, y0);
}

// ---------------- prepass ----------------
__device__ __forceinline__ void split1(float x, __half& h, __half& l) {
    h = __float2half_rn(x);
    l = __float2half_rn((x - __half2float(h)) * 2048.0f);
}
__global__ void split_x_kernel(const float4* __restrict__ in, __half* __restrict__ hi,
                               __half* __restrict__ lo, int n4) {
    int i = blockIdx.x * blockDim.x + threadIdx.x;
    if (i >= n4) return;
    float4 v = in[i];
    __half h[4], l[4];
    split1(v.x, h[0], l[0]); split1(v.y, h[1], l[1]);
    split1(v.z, h[2], l[2]); split1(v.w, h[3], l[3]);
    *(uint2*)(hi + (size_t)i * 4) = *(uint2*)h;
    *(uint2*)(lo + (size_t)i * 4) = *(uint2*)l;
}
// in: [R, C] f32 -> hi/lo: [C, R] fp16 (transpose + split)
__global__ void transpose_split_kernel(const float* __restrict__ in, __half* __restrict__ hi,
                                       __half* __restrict__ lo, int R, int C) {
    __shared__ float t[32][33];
    int c0 = blockIdx.x * 32, r0 = blockIdx.y * 32;
    int tx = threadIdx.x, ty = threadIdx.y;   // 32 x 8
    #pragma unroll
    for (int i = 0; i < 32; i += 8)
        t[ty + i][tx] = in[(size_t)(r0 + ty + i) * C + c0 + tx];
    __syncthreads();
    #pragma unroll
    for (int i = 0; i < 32; i += 8) {
        __half h, l; split1(t[tx][ty + i], h, l);
        size_t o = (size_t)(c0 + ty + i) * R + r0 + tx;
        hi[o] = h; lo[o] = l;
    }
}

// ---------------- main GEMM ----------------
// C[M,N] = A[M,K] @ B[N,K]^T (+bias, q8, optional PWL-GELU)
// 8 warps in 2x4 grid, warp tile 64x32.
// CH16=true  (GEMM1): chain-16 main -> SMEM masters; R13 per-chunk pipeline.
// CH16=false (GEMM2): plain full-K chain; mega-stage pipe (2 chunks/sync).
template<bool HAS_ALO, bool GELU, bool CH16, int NST>
__global__ void __launch_bounds__(NTHREADS, 1)
gemm_mma(const __half* __restrict__ A, const __half* __restrict__ Alo,
         const __half* __restrict__ B, const __half* __restrict__ Blo,
         const float* __restrict__ bias,
         __half* __restrict__ outH, float* __restrict__ outF,
         int K, int N)
{
    constexpr int OFF_ALO = 16384;
    constexpr int OFF_BHI = HAS_ALO ? 32768 : 16384;
    constexpr int OFF_BLO = OFF_BHI + 16384;
    constexpr int SBYTES  = HAS_ALO ? 65536 : 49152;
    constexpr int PD      = NST - 1;          // prefetch distance (chunk path)

    extern __shared__ char smem[];
    const uint32_t sb = smem_u32(smem);
    float* mst = (float*)(smem + NST * SBYTES);   // masters (CH16 only)
    __shared__ float Ys[33];

    const int tid = threadIdx.x;
    const int wid = tid >> 5, l = tid & 31;
    const int mTile = blockIdx.y * BM, nTile = blockIdx.x * BN;
    const int warpM = wid & 1, warpN = wid >> 1;   // 2x4 warp grid
    const int m0 = warpM * 64, n0 = warpN * 32;
    const int nK = K / BK;

    if (GELU && tid < 33) Ys[tid] = d_pwl_y[tid];

    if (CH16) {
        #pragma unroll
        for (int j = 0; j < 64; j++) mst[j * NTHREADS + tid] = 0.0f;
    }

    // ---- ldmatrix address precompute ----
    const uint32_t rx = (uint32_t)((l & 7) << 4);
    uint32_t kpA[4], kpB[4];
    #pragma unroll
    for (int ks = 0; ks < 4; ks++) {
        kpA[ks] = ((uint32_t)(ks * 32 + ((l >> 4) << 4))) ^ rx;
        kpB[ks] = ((uint32_t)(ks * 32 + (((l >> 3) & 1) << 4))) ^ rx;
    }
    uint32_t aoff[4], boff[2];
    #pragma unroll
    for (int mt = 0; mt < 4; mt++) aoff[mt] = (uint32_t)((m0 + mt * 16 + (l & 15)) * 128);
    #pragma unroll
    for (int p = 0; p < 2; p++)
        boff[p] = (uint32_t)((n0 + p * 16 + ((l >> 4) << 3) + (l & 7)) * 128);

    float    cm[4][4][4];    // main f32 (chain or full accumulator)
    uint32_t accx[4][4][2];  // cross (x2048) in f16 accumulators
    #pragma unroll
    for (int mt = 0; mt < 4; mt++)
        #pragma unroll
        for (int t = 0; t < 4; t++) {
            if (!CH16) {
                #pragma unroll
                for (int j = 0; j < 4; j++) cm[mt][t][j] = 0.0f;
            }
            accx[mt][t][0] = 0u; accx[mt][t][1] = 0u;
        }

    // ---- stage loader (256 threads: 4 chunks of 16B per 16KB tile) ----
    auto load_stage = [&](int kt, int s) {
        const uint32_t sbase = sb + s * SBYTES;
        const int k0 = kt * BK;
        #pragma unroll
        for (int i = 0; i < 4; i++) {
            int c = tid + i * NTHREADS;
            int r = c >> 3, cc = c & 7;
            uint32_t so = SWZ((uint32_t)(r * 128 + cc * 16));
            const __half* gA = A + (size_t)(mTile + r) * K + k0 + cc * 8;
            CP16(sbase + so, gA);
            if (HAS_ALO) {
                const __half* gAl = Alo + (size_t)(mTile + r) * K + k0 + cc * 8;
                CP16(sbase + OFF_ALO + so, gAl);
            }
            const __half* gB  = B   + (size_t)(nTile + r) * K + k0 + cc * 8;
            const __half* gBl = Blo + (size_t)(nTile + r) * K + k0 + cc * 8;
            CP16(sbase + OFF_BHI + so, gB);
            CP16(sbase + OFF_BLO + so, gBl);
        }
    };

    // one BK-chunk of compute (R13 verbatim); Z starts the main chain.
    // Three-pass MMA issue per ks.
    auto chunk = [&](auto ZC, int kt) {
        constexpr bool Z = decltype(ZC)::value;
        cp_wait<PD - 1>();
        __syncthreads();
        if (kt + PD < nK) load_stage(kt + PD, (kt + PD) % NST);
        CP_COMMIT();

        const uint32_t st = sb + (kt % NST) * SBYTES;
        #pragma unroll
        for (int ks = 0; ks < 4; ks++) {
            uint32_t ah[4][4], al[4][4];
            uint32_t bh[2][4], bl[2][4];
            #pragma unroll
            for (int p = 0; p < 2; p++) {
                ldsm4(bh[p], st + OFF_BHI + boff[p] + kpB[ks]);
                ldsm4(bl[p], st + OFF_BLO + boff[p] + kpB[ks]);
            }
            #pragma unroll
            for (int mt = 0; mt < 4; mt++) {
                ldsm4(ah[mt], st + aoff[mt] + kpA[ks]);
                if (HAS_ALO) ldsm4(al[mt], st + OFF_ALO + aoff[mt] + kpA[ks]);
            }
            // ---- pass 1: main ----
            #pragma unroll
            for (int p = 0; p < 2; p++)
                #pragma unroll
                for (int tt = 0; tt < 2; tt++) {
                    const int t = p * 2 + tt;
                    const uint32_t h0 = bh[p][tt * 2], h1 = bh[p][tt * 2 + 1];
                    #pragma unroll
                    for (int mt = 0; mt < 4; mt++) {
                        if (Z && ks == 0) mma16816_z(cm[mt][t], ah[mt], h0, h1);
                        else              mma16816  (cm[mt][t], ah[mt], h0, h1);
                    }
                }
            // ---- pass 2: cross hi*lo ----
            #pragma unroll
            for (int p = 0; p < 2; p++)
                #pragma unroll
                for (int tt = 0; tt < 2; tt++) {
                    const int t = p * 2 + tt;
                    const uint32_t l0 = bl[p][tt * 2], l1 = bl[p][tt * 2 + 1];
                    #pragma unroll
                    for (int mt = 0; mt < 4; mt++)
                        mma16816_h(accx[mt][t], ah[mt], l0, l1);
                }
            // ---- pass 3: cross lo*hi ----
            if (HAS_ALO) {
                #pragma unroll
                for (int p = 0; p < 2; p++)
                    #pragma unroll
                    for (int tt = 0; tt < 2; tt++) {
                        const int t = p * 2 + tt;
                        const uint32_t h0 = bh[p][tt * 2], h1 = bh[p][tt * 2 + 1];
                        #pragma unroll
                        for (int mt = 0; mt < 4; mt++)
                            mma16816_h(accx[mt][t], al[mt], h0, h1);
                    }
            }
        }
    };

    // ks-body for the G2 mega-stage path (no wait/load; plain main chain)
    auto g2_ks = [&](uint32_t st, int ks) {
        uint32_t ah[4][4];
        uint32_t bh[2][4], bl[2][4];
        #pragma unroll
        for (int p = 0; p < 2; p++) {
            ldsm4(bh[p], st + OFF_BHI + boff[p] + kpB[ks]);
            ldsm4(bl[p], st + OFF_BLO + boff[p] + kpB[ks]);
        }
        #pragma unroll
        for (int mt = 0; mt < 4; mt++)
            ldsm4(ah[mt], st + aoff[mt] + kpA[ks]);
        #pragma unroll
        for (int p = 0; p < 2; p++)
            #pragma unroll
            for (int tt = 0; tt < 2; tt++) {
                const int t = p * 2 + tt;
                const uint32_t h0 = bh[p][tt * 2], h1 = bh[p][tt * 2 + 1];
                #pragma unroll
                for (int mt = 0; mt < 4; mt++)
                    mma16816(cm[mt][t], ah[mt], h0, h1);
            }
        #pragma unroll
        for (int p = 0; p < 2; p++)
            #pragma unroll
            for (int tt = 0; tt < 2; tt++) {
                const int t = p * 2 + tt;
                const uint32_t l0 = bl[p][tt * 2], l1 = bl[p][tt * 2 + 1];
                #pragma unroll
                for (int mt = 0; mt < 4; mt++)
                    mma16816_h(accx[mt][t], ah[mt], l0, l1);
            }
    };

    if (CH16) {
        // ---- G1: R13 pipeline verbatim ----
        #pragma unroll
        for (int i = 0; i < PD; i++) { load_stage(i, i); CP_COMMIT(); }
        for (int kg = 0; kg < nK / 4; kg++) {
            chunk(std::true_type{},  4 * kg);
            chunk(std::false_type{}, 4 * kg + 1);
            chunk(std::false_type{}, 4 * kg + 2);
            chunk(std::false_type{}, 4 * kg + 3);
            // RN flush of the chain-16 group into SMEM masters
            #pragma unroll
            for (int mt = 0; mt < 4; mt++)
                #pragma unroll
                for (int t = 0; t < 4; t++)
                    #pragma unroll
                    for (int j = 0; j < 4; j++) {
                        const int idx = (mt * 4 + t) * 4 + j;
                        mst[idx * NTHREADS + tid] += cm[mt][t][j];
                    }
        }
    } else {
        // ---- G2: mega-stage pipeline: 4 slots, 2 chunks per sync ----
        load_stage(0, 0); CP_COMMIT();
        load_stage(1, 1); CP_COMMIT();
        for (int kp = 0; kp < nK; kp += 2) {
            cp_wait<0>();
            __syncthreads();
            // prefetch next pair into slots freed by the PREVIOUS iteration
            if (kp + 2 < nK) { load_stage(kp + 2, (kp + 2) & 3); CP_COMMIT(); }
            if (kp + 3 < nK) { load_stage(kp + 3, (kp + 3) & 3); CP_COMMIT(); }
            const uint32_t st0 = sb + (kp & 3) * SBYTES;
            const uint32_t st1 = sb + ((kp + 1) & 3) * SBYTES;
            #pragma unroll
            for (int ks = 0; ks < 4; ks++) g2_ks(st0, ks);
            #pragma unroll
            for (int ks = 0; ks < 4; ks++) g2_ks(st1, ks);
        }
    }

    // ---- epilogue: v = main + cross_f16/2048 + bias ----
    const float invS = 4.8828125e-4f;   // 1/2048
    const int rg = mTile + m0 + (l >> 2);
    const int cg = nTile + n0 + (l & 3) * 2;
    #pragma unroll
    for (int mt = 0; mt < 4; mt++) {
        const int r0r = rg + mt * 16;
        #pragma unroll
        for (int t = 0; t < 4; t++) {
            const int col = cg + t * 8;
            const float b0 = __ldg(bias + col), b1 = __ldg(bias + col + 1);
            const __half2 c01 = *(const __half2*)&accx[mt][t][0];
            const __half2 c23 = *(const __half2*)&accx[mt][t][1];
            float m0v, m1v, m2v, m3v;
            if (CH16) {
                const int ib = (mt * 4 + t) * 4;
                m0v = mst[(ib + 0) * NTHREADS + tid];
                m1v = mst[(ib + 1) * NTHREADS + tid];
                m2v = mst[(ib + 2) * NTHREADS + tid];
                m3v = mst[(ib + 3) * NTHREADS + tid];
            } else {
                m0v = cm[mt][t][0]; m1v = cm[mt][t][1];
                m2v = cm[mt][t][2]; m3v = cm[mt][t][3];
            }
            float v0 = fmaf(__half2float(__low2half(c01)),  invS, m0v) + b0;
            float v1 = fmaf(__half2float(__high2half(c01)), invS, m1v) + b1;
            float v2 = fmaf(__half2float(__low2half(c23)),  invS, m2v) + b0;
            float v3 = fmaf(__half2float(__high2half(c23)), invS, m3v) + b1;
            if (GELU) {
                v0 = q8(gelu_pwl(q8(v0), Ys)); v1 = q8(gelu_pwl(q8(v1), Ys));
                v2 = q8(gelu_pwl(q8(v2), Ys)); v3 = q8(gelu_pwl(q8(v3), Ys));
                *(__half2*)(outH + (size_t)r0r * N + col) =
                    __halves2half2(__float2half_rn(v0), __float2half_rn(v1));
                *(__half2*)(outH + (size_t)(r0r + 8) * N + col) =
                    __halves2half2(__float2half_rn(v2), __float2half_rn(v3));
            } else {
                float2 o0 = {q8(v0), q8(v1)}, o1 = {q8(v2), q8(v3)};
                *(float2*)(outF + (size_t)r0r * N + col) = o0;
                *(float2*)(outF + (size_t)(r0r + 8) * N + col) = o1;
            }
        }
    }
}

extern "C" void kernel_launch(void* const* d_in, const int* in_sizes, int n_in,
                              void* d_out, int out_size)
{
    const float* x  = (const float*)d_in[0];
    const float* w1 = (const float*)d_in[1];
    const float* b1 = (const float*)d_in[2];
    const float* w2 = (const float*)d_in[3];
    const float* b2 = (const float*)d_in[4];
    float* out = (float*)d_out;

    __half *a1hi, *a1lo, *w1thi, *w1tlo, *hbuf, *w2thi, *w2tlo;
    cudaGetSymbolAddress((void**)&a1hi, g_a1hi);
    cudaGetSymbolAddress((void**)&a1lo, g_a1lo);
    cudaGetSymbolAddress((void**)&w1thi, g_w1thi);
    cudaGetSymbolAddress((void**)&w1tlo, g_w1tlo);
    cudaGetSymbolAddress((void**)&hbuf, g_hbuf);
    cudaGetSymbolAddress((void**)&w2thi, g_w2thi);
    cudaGetSymbolAddress((void**)&w2tlo, g_w2tlo);

    int n4 = M_ROWS * D_DIM / 4;
    split_x_kernel<<<(n4 + 255) / 256, 256>>>((const float4*)x, a1hi, a1lo, n4);
    transpose_split_kernel<<<dim3(F_DIM / 32, D_DIM / 32), dim3(32, 8)>>>(w1, w1thi, w1tlo, D_DIM, F_DIM);
    transpose_split_kernel<<<dim3(D_DIM / 32, F_DIM / 32), dim3(32, 8)>>>(w2, w2thi, w2tlo, F_DIM, D_DIM);

    constexpr int SMEM1 = 2 * 65536 + 65536;   // 2 stages + masters = 192 KB
    constexpr int SMEM2 = 4 * 49152;           // 4 slots           = 192 KB
    cudaFuncSetAttribute((const void*)gemm_mma<true,  true,  true,  2>,
                         cudaFuncAttributeMaxDynamicSharedMemorySize, SMEM1);
    cudaFuncSetAttribute((const void*)gemm_mma<false, false, false, 4>,
                         cudaFuncAttributeMaxDynamicSharedMemorySize, SMEM2);

    // GEMM1: [16384,1024] x [4096,1024]^T -> h (gelu+q8, fp16); R13 pipeline
    gemm_mma<true, true, true, 2><<<dim3(F_DIM / BN, M_ROWS / BM), NTHREADS, SMEM1>>>(
        a1hi, a1lo, w1thi, w1tlo, b1, hbuf, nullptr, D_DIM, F_DIM);
    // GEMM2: [16384,4096] x [1024,4096]^T -> out (q8, f32); mega-stage pipe
    gemm_mma<false, false, false, 4><<<dim3(D_DIM / BN, M_ROWS / BM), NTHREADS, SMEM2>>>(
        hbuf, hbuf, w2thi, w2tlo, b2, nullptr, out, F_DIM, D_DIM);
}